// round 16
// baseline (speedup 1.0000x reference)
#include <cuda_runtime.h>
#include <cuda_bf16.h>
#include <cstdint>

#define HH 256
#define WW 256
#define HWP 65536
#define CC 64
#define BB 4

// ---------------------------------------------------------------- scratch
__device__ __align__(16) __nv_bfloat16 g_th[(size_t)BB * HWP * CC];  // [b][p][c] hi
__device__ __align__(16) __nv_bfloat16 g_tl[(size_t)BB * HWP * CC];  // [b][p][c] lo
__device__ uint4 g_wfh[9 * 4 * 4 * 32];    // conv weights frag-order hi
__device__ uint4 g_wfl[9 * 4 * 4 * 32];    // lo
__device__ uint4 g_wqh[12 * 4 * 32];       // qkv weights frag-order hi
__device__ uint4 g_wql[12 * 4 * 32];       // lo

#define BFLO(u) __uint_as_float((u) << 16)
#define BFHI(u) __uint_as_float((u) & 0xffff0000u)

// ---------------------------------------------------------------------------
__device__ __forceinline__ void mma16816(float& d0, float& d1, float& d2, float& d3,
                                         uint32_t a0, uint32_t a1, uint32_t a2, uint32_t a3,
                                         uint32_t b0, uint32_t b1) {
    asm volatile(
        "mma.sync.aligned.m16n8k16.row.col.f32.bf16.bf16.f32 "
        "{%0,%1,%2,%3}, {%4,%5,%6,%7}, {%8,%9}, {%0,%1,%2,%3};"
        : "+f"(d0), "+f"(d1), "+f"(d2), "+f"(d3)
        : "r"(a0), "r"(a1), "r"(a2), "r"(a3), "r"(b0), "r"(b1));
}

__device__ __forceinline__ void ldmx4(uint32_t& r0, uint32_t& r1, uint32_t& r2,
                                      uint32_t& r3, uint32_t saddr) {
    asm volatile("ldmatrix.sync.aligned.m8n8.x4.shared.b16 {%0,%1,%2,%3}, [%4];"
                 : "=r"(r0), "=r"(r1), "=r"(r2), "=r"(r3) : "r"(saddr));
}

__device__ __forceinline__ void ldmx2(uint32_t& r0, uint32_t& r1, uint32_t saddr) {
    asm volatile("ldmatrix.sync.aligned.m8n8.x2.shared.b16 {%0,%1}, [%2];"
                 : "=r"(r0), "=r"(r1) : "r"(saddr));
}

__device__ __forceinline__ void bfpair(float w0, float w1, uint32_t& h, uint32_t& l) {
    __nv_bfloat16 h0 = __float2bfloat16_rn(w0);
    __nv_bfloat16 h1 = __float2bfloat16_rn(w1);
    __nv_bfloat16 l0 = __float2bfloat16_rn(w0 - __bfloat162float(h0));
    __nv_bfloat16 l1 = __float2bfloat16_rn(w1 - __bfloat162float(h1));
    h = (uint32_t)__bfloat16_as_ushort(h0) | ((uint32_t)__bfloat16_as_ushort(h1) << 16);
    l = (uint32_t)__bfloat16_as_ushort(l0) | ((uint32_t)__bfloat16_as_ushort(l1) << 16);
}

// ---------------------------------------------------------------------------
// Kernel 0: merged weight prep (unchanged).
// ---------------------------------------------------------------------------
__global__ void prep_kernel(const float* __restrict__ wm,
                            const float* __restrict__ wq) {
    if (blockIdx.x < 18) {
        int e = blockIdx.x * 256 + threadIdx.x;
        if (e >= 4608) return;
        int tap = e / 512, rem = e & 511;
        int ocg = rem >> 7, rem2 = rem & 127;
        int ks = rem2 >> 5, lane = rem2 & 31;
        int qt = lane >> 2, rt = lane & 3;
        int oc = ocg * 16 + qt, c = ks * 16 + 2 * rt;
        uint4 hv, lv;
        bfpair(wm[oc * 576 + c * 9 + tap],       wm[oc * 576 + (c + 1) * 9 + tap],       hv.x, lv.x);
        bfpair(wm[(oc + 8) * 576 + c * 9 + tap], wm[(oc + 8) * 576 + (c + 1) * 9 + tap], hv.y, lv.y);
        bfpair(wm[oc * 576 + (c + 8) * 9 + tap], wm[oc * 576 + (c + 9) * 9 + tap],       hv.z, lv.z);
        bfpair(wm[(oc + 8) * 576 + (c + 8) * 9 + tap], wm[(oc + 8) * 576 + (c + 9) * 9 + tap], hv.w, lv.w);
        g_wfh[e] = hv;
        g_wfl[e] = lv;
    } else {
        int e = (blockIdx.x - 18) * 256 + threadIdx.x;
        if (e >= 1536) return;
        int lane = e & 31, ks = (e >> 5) & 3, ocg = e >> 7;
        int qt = lane >> 2, rt = lane & 3;
        int oc = ocg * 16 + qt, c = ks * 16 + 2 * rt;
        uint4 hv, lv;
        bfpair(wq[oc * 64 + c],           wq[oc * 64 + c + 1],           hv.x, lv.x);
        bfpair(wq[(oc + 8) * 64 + c],     wq[(oc + 8) * 64 + c + 1],     hv.y, lv.y);
        bfpair(wq[oc * 64 + c + 8],       wq[oc * 64 + c + 9],           hv.z, lv.z);
        bfpair(wq[(oc + 8) * 64 + c + 8], wq[(oc + 8) * 64 + c + 9],     hv.w, lv.w);
        g_wqh[e] = hv;
        g_wql[e] = lv;
    }
}

// ---------------------------------------------------------------------------
// Kernel 1: FUSED qkv (HMMA) + window attention + residual.
// R16: phase-2 retiled — warp = (m-pair 0..5, nt-half 0..1): 2 m-tiles x 7 nt,
// B fragments shared by 6 warps instead of 12 (L1 bytes halved). nt-half is
// processed in 2 sub-chunks (4 nt, 3 nt) with per-sub epilogue to cap live
// acc regs at 32. ks order per nt unchanged -> bitwise-identical results.
// ---------------------------------------------------------------------------
#define HWD 18
#define HPXN 108
#define HPAD 112
#define XSTR 36
#define APS 68
#define OFF_XL (HPAD * XSTR)                 // 4032  u32
#define OFF_QB (2 * HPAD * XSTR)             // 8064
#define OFF_KB (OFF_QB + 64 * APS)           // 12416
#define OFF_VB (OFF_KB + HPAD * APS)         // 20032
#define FUSED_SMEM ((OFF_VB + HPAD * APS) * 4)   // 110592 B

__global__ __launch_bounds__(384, 2) void fused_kernel(const float* __restrict__ x,
                                                       const float* __restrict__ bq) {
    extern __shared__ uint32_t fs[];
    uint32_t* xh32 = fs;
    uint32_t* xl32 = fs + OFF_XL;
    float* qbuf = (float*)(fs + OFF_QB);
    float* kbuf = (float*)(fs + OFF_KB);
    float* vbuf = (float*)(fs + OFF_VB);

    const int tid = threadIdx.x;
    const int wid = tid >> 5, lane = tid & 31;
    const int qt = lane >> 2, rt = lane & 3;
    const int x0 = blockIdx.x * 16, y0 = blockIdx.y * 4;
    const int b = blockIdx.z;

    // ---- Phase 1: stage x halo as bf16 hi/lo pairs ----
    for (int e = tid; e < 512; e += 384) {     // 4 c-groups x 128 hp slots
        int hp = e & 127;
        int g4 = e >> 7;
        if (hp >= HPAD) continue;
        int hy = hp / HWD, hx = hp - hy * HWD;
        int gy = y0 - 1 + hy, gx = x0 - 1 + hx;
        bool ok = (hp < HPXN) && gy >= 0 && gy < HH && gx >= 0 && gx < WW;
        const float* xp = x + (size_t)b * CC * HWP + gy * WW + gx;
        #pragma unroll
        for (int j = 0; j < 8; j++) {
            int c = g4 * 16 + 2 * j;
            float v0 = 0.f, v1 = 0.f;
            if (ok) { v0 = xp[(size_t)c * HWP]; v1 = xp[(size_t)(c + 1) * HWP]; }
            uint32_t h, l;
            bfpair(v0, v1, h, l);
            xh32[hp * XSTR + (c >> 1)] = h;
            xl32[hp * XSTR + (c >> 1)] = l;
        }
    }
    __syncthreads();

    // ---- Phase 2: qkv MMA, (m-pair x nt-half) warp tiling ----
    {
        const int mpair  = wid >> 1;           // 0..5
        const int nthalf = wid & 1;            // 0..1
        const int ntb = nthalf * 7;
        const int chunk = mpair >> 1;          // 0=q 1=k 2=v
        const bool isq = (chunk == 0);
        float* dst = (chunk == 1) ? kbuf : vbuf;

        const float b00 = __ldg(bq + (mpair * 2 + 0) * 16 + qt);
        const float b10 = __ldg(bq + (mpair * 2 + 0) * 16 + qt + 8);
        const float b01 = __ldg(bq + (mpair * 2 + 1) * 16 + qt);
        const float b11 = __ldg(bq + (mpair * 2 + 1) * 16 + qt + 8);

        const uint4* wqh0 = g_wqh + (mpair * 2 + 0) * 128 + lane;
        const uint4* wql0 = g_wql + (mpair * 2 + 0) * 128 + lane;
        const uint4* wqh1 = g_wqh + (mpair * 2 + 1) * 128 + lane;
        const uint4* wql1 = g_wql + (mpair * 2 + 1) * 128 + lane;

        const int lm_m = lane >> 3, lm_r = lane & 7;
        const uint32_t sbx = (uint32_t)__cvta_generic_to_shared(xh32);
        const uint32_t lo4 = (uint32_t)(((lm_m >> 1) * 8 + lm_r) * XSTR + (lm_m & 1) * 4) * 4u;
        const uint32_t lo2 = (uint32_t)((lane & 7) * XSTR + ((lane >> 3) & 1) * 4) * 4u;
        const uint32_t XLB = (uint32_t)OFF_XL * 4u;

        #pragma unroll
        for (int sub = 0; sub < 2; sub++) {
            float acc[2][4][4];
            #pragma unroll
            for (int mt = 0; mt < 2; mt++)
                #pragma unroll
                for (int sl = 0; sl < 4; sl++)
                    #pragma unroll
                    for (int i = 0; i < 4; i++) acc[mt][sl][i] = 0.0f;

            #pragma unroll
            for (int ks = 0; ks < 4; ks++) {
                uint4 Wh0 = __ldg(wqh0 + ks * 32);
                uint4 Wl0 = __ldg(wql0 + ks * 32);
                uint4 Wh1 = __ldg(wqh1 + ks * 32);
                uint4 Wl1 = __ldg(wql1 + ks * 32);
                const uint32_t kob = (uint32_t)(ks * 8) * 4u;

                if (sub == 0) {
                    #pragma unroll
                    for (int p = 0; p < 2; p++) {
                        if (isq && nthalf == 0 && p == 0) continue;   // nt 0,1 outside center
                        const uint32_t ra = sbx + lo4
                            + (uint32_t)((ntb + 2 * p) * 8 * XSTR) * 4u + kob;
                        uint32_t bh0, bh1, bh2, bh3, bl0, bl1, bl2, bl3;
                        ldmx4(bh0, bh1, bh2, bh3, ra);
                        ldmx4(bl0, bl1, bl2, bl3, ra + XLB);
                        mma16816(acc[0][2*p][0], acc[0][2*p][1], acc[0][2*p][2], acc[0][2*p][3],
                                 Wh0.x, Wh0.y, Wh0.z, Wh0.w, bh0, bh1);
                        mma16816(acc[0][2*p][0], acc[0][2*p][1], acc[0][2*p][2], acc[0][2*p][3],
                                 Wl0.x, Wl0.y, Wl0.z, Wl0.w, bh0, bh1);
                        mma16816(acc[0][2*p][0], acc[0][2*p][1], acc[0][2*p][2], acc[0][2*p][3],
                                 Wh0.x, Wh0.y, Wh0.z, Wh0.w, bl0, bl1);
                        mma16816(acc[0][2*p+1][0], acc[0][2*p+1][1], acc[0][2*p+1][2], acc[0][2*p+1][3],
                                 Wh0.x, Wh0.y, Wh0.z, Wh0.w, bh2, bh3);
                        mma16816(acc[0][2*p+1][0], acc[0][2*p+1][1], acc[0][2*p+1][2], acc[0][2*p+1][3],
                                 Wl0.x, Wl0.y, Wl0.z, Wl0.w, bh2, bh3);
                        mma16816(acc[0][2*p+1][0], acc[0][2*p+1][1], acc[0][2*p+1][2], acc[0][2*p+1][3],
                                 Wh0.x, Wh0.y, Wh0.z, Wh0.w, bl2, bl3);
                        mma16816(acc[1][2*p][0], acc[1][2*p][1], acc[1][2*p][2], acc[1][2*p][3],
                                 Wh1.x, Wh1.y, Wh1.z, Wh1.w, bh0, bh1);
                        mma16816(acc[1][2*p][0], acc[1][2*p][1], acc[1][2*p][2], acc[1][2*p][3],
                                 Wl1.x, Wl1.y, Wl1.z, Wl1.w, bh0, bh1);
                        mma16816(acc[1][2*p][0], acc[1][2*p][1], acc[1][2*p][2], acc[1][2*p][3],
                                 Wh1.x, Wh1.y, Wh1.z, Wh1.w, bl0, bl1);
                        mma16816(acc[1][2*p+1][0], acc[1][2*p+1][1], acc[1][2*p+1][2], acc[1][2*p+1][3],
                                 Wh1.x, Wh1.y, Wh1.z, Wh1.w, bh2, bh3);
                        mma16816(acc[1][2*p+1][0], acc[1][2*p+1][1], acc[1][2*p+1][2], acc[1][2*p+1][3],
                                 Wl1.x, Wl1.y, Wl1.z, Wl1.w, bh2, bh3);
                        mma16816(acc[1][2*p+1][0], acc[1][2*p+1][1], acc[1][2*p+1][2], acc[1][2*p+1][3],
                                 Wh1.x, Wh1.y, Wh1.z, Wh1.w, bl2, bl3);
                    }
                } else {
                    // pair p=2 -> slots 0,1 (nt local 4,5)
                    {
                        const uint32_t ra = sbx + lo4
                            + (uint32_t)((ntb + 4) * 8 * XSTR) * 4u + kob;
                        uint32_t bh0, bh1, bh2, bh3, bl0, bl1, bl2, bl3;
                        ldmx4(bh0, bh1, bh2, bh3, ra);
                        ldmx4(bl0, bl1, bl2, bl3, ra + XLB);
                        mma16816(acc[0][0][0], acc[0][0][1], acc[0][0][2], acc[0][0][3],
                                 Wh0.x, Wh0.y, Wh0.z, Wh0.w, bh0, bh1);
                        mma16816(acc[0][0][0], acc[0][0][1], acc[0][0][2], acc[0][0][3],
                                 Wl0.x, Wl0.y, Wl0.z, Wl0.w, bh0, bh1);
                        mma16816(acc[0][0][0], acc[0][0][1], acc[0][0][2], acc[0][0][3],
                                 Wh0.x, Wh0.y, Wh0.z, Wh0.w, bl0, bl1);
                        mma16816(acc[0][1][0], acc[0][1][1], acc[0][1][2], acc[0][1][3],
                                 Wh0.x, Wh0.y, Wh0.z, Wh0.w, bh2, bh3);
                        mma16816(acc[0][1][0], acc[0][1][1], acc[0][1][2], acc[0][1][3],
                                 Wl0.x, Wl0.y, Wl0.z, Wl0.w, bh2, bh3);
                        mma16816(acc[0][1][0], acc[0][1][1], acc[0][1][2], acc[0][1][3],
                                 Wh0.x, Wh0.y, Wh0.z, Wh0.w, bl2, bl3);
                        mma16816(acc[1][0][0], acc[1][0][1], acc[1][0][2], acc[1][0][3],
                                 Wh1.x, Wh1.y, Wh1.z, Wh1.w, bh0, bh1);
                        mma16816(acc[1][0][0], acc[1][0][1], acc[1][0][2], acc[1][0][3],
                                 Wl1.x, Wl1.y, Wl1.z, Wl1.w, bh0, bh1);
                        mma16816(acc[1][0][0], acc[1][0][1], acc[1][0][2], acc[1][0][3],
                                 Wh1.x, Wh1.y, Wh1.z, Wh1.w, bl0, bl1);
                        mma16816(acc[1][1][0], acc[1][1][1], acc[1][1][2], acc[1][1][3],
                                 Wh1.x, Wh1.y, Wh1.z, Wh1.w, bh2, bh3);
                        mma16816(acc[1][1][0], acc[1][1][1], acc[1][1][2], acc[1][1][3],
                                 Wl1.x, Wl1.y, Wl1.z, Wl1.w, bh2, bh3);
                        mma16816(acc[1][1][0], acc[1][1][1], acc[1][1][2], acc[1][1][3],
                                 Wh1.x, Wh1.y, Wh1.z, Wh1.w, bl2, bl3);
                    }
                    // single nt (local 6) -> slot 2; q-warps skip on nthalf 1 (nt 13)
                    if (!(isq && nthalf == 1)) {
                        const uint32_t ra = sbx + lo2
                            + (uint32_t)((ntb + 6) * 8 * XSTR) * 4u + kob;
                        uint32_t bh0, bh1, bl0, bl1;
                        ldmx2(bh0, bh1, ra);
                        ldmx2(bl0, bl1, ra + XLB);
                        mma16816(acc[0][2][0], acc[0][2][1], acc[0][2][2], acc[0][2][3],
                                 Wh0.x, Wh0.y, Wh0.z, Wh0.w, bh0, bh1);
                        mma16816(acc[0][2][0], acc[0][2][1], acc[0][2][2], acc[0][2][3],
                                 Wl0.x, Wl0.y, Wl0.z, Wl0.w, bh0, bh1);
                        mma16816(acc[0][2][0], acc[0][2][1], acc[0][2][2], acc[0][2][3],
                                 Wh0.x, Wh0.y, Wh0.z, Wh0.w, bl0, bl1);
                        mma16816(acc[1][2][0], acc[1][2][1], acc[1][2][2], acc[1][2][3],
                                 Wh1.x, Wh1.y, Wh1.z, Wh1.w, bh0, bh1);
                        mma16816(acc[1][2][0], acc[1][2][1], acc[1][2][2], acc[1][2][3],
                                 Wl1.x, Wl1.y, Wl1.z, Wl1.w, bh0, bh1);
                        mma16816(acc[1][2][0], acc[1][2][1], acc[1][2][2], acc[1][2][3],
                                 Wh1.x, Wh1.y, Wh1.z, Wh1.w, bl0, bl1);
                    }
                }
            }

            // ---- per-sub epilogue ----
            const int nslots = (sub == 0) ? 4 : 3;
            for (int sl = 0; sl < nslots; sl++) {
                const int nt = ntb + (sub == 0 ? sl : 4 + sl);
                #pragma unroll
                for (int j = 0; j < 2; j++) {
                    int hpj = nt * 8 + 2 * rt + j;
                    int hy = hpj / HWD, hx = hpj - hy * HWD;
                    #pragma unroll
                    for (int mt = 0; mt < 2; mt++) {
                        const int ocl = (mpair & 1) * 32 + mt * 16 + qt;
                        const float bv0 = mt ? b01 : b00;
                        const float bv1 = mt ? b11 : b10;
                        if (chunk == 0) {
                            if (hy >= 1 && hy <= 4 && hx >= 1 && hx <= 16) {
                                int ci = (hy - 1) * 16 + (hx - 1);
                                qbuf[ci * APS + ocl]     = acc[mt][sl][j]     + bv0;
                                qbuf[ci * APS + ocl + 8] = acc[mt][sl][2 + j] + bv1;
                            }
                        } else {
                            int gy = y0 - 1 + hy, gx = x0 - 1 + hx;
                            bool ok = (hpj < HPXN) && gy >= 0 && gy < HH && gx >= 0 && gx < WW;
                            dst[hpj * APS + ocl]     = ok ? acc[mt][sl][j]     + bv0 : 0.0f;
                            dst[hpj * APS + ocl + 8] = ok ? acc[mt][sl][2 + j] + bv1 : 0.0f;
                        }
                    }
                }
            }
        }
    }
    __syncthreads();

    // ---- Phase 3: attention from smem (unchanged) ----
    const int g = lane >> 3, cl = lane & 7;
    #pragma unroll
    for (int iter = 0; iter < 2; iter++) {
        const int pxi = iter * 48 + wid * 4 + g;   // 0..95
        if (pxi >= 64) break;                       // iter1: wid<4 only
        const int tx = pxi & 15, ty = pxi >> 4;
        const int hp = (ty + 1) * HWD + (tx + 1);
        const int p = (y0 + ty) * WW + x0 + tx;

        float4 q0 = *(const float4*)(qbuf + pxi * APS + cl * 4);
        float4 q1 = *(const float4*)(qbuf + pxi * APS + cl * 4 + 32);
        const int base = hp * APS + cl * 4;

        float d[9];
        #pragma unroll
        for (int n = 0; n < 9; n++) {
            int dy = n / 3 - 1, dx = n - (n / 3) * 3 - 1;
            const float* kr = kbuf + base + (dy * HWD + dx) * APS;
            float4 k0 = *(const float4*)kr;
            float4 k1 = *(const float4*)(kr + 32);
            d[n] = q0.x * k0.x + q0.y * k0.y + q0.z * k0.z + q0.w * k0.w
                 + q1.x * k1.x + q1.y * k1.y + q1.z * k1.z + q1.w * k1.w;
        }
        #pragma unroll
        for (int ofs = 4; ofs > 0; ofs >>= 1)
            #pragma unroll
            for (int n = 0; n < 9; n++)
                d[n] += __shfl_xor_sync(0xffffffffu, d[n], ofs);

        float m = -1e30f;
        #pragma unroll
        for (int n = 0; n < 9; n++) { d[n] *= 0.125f; m = fmaxf(m, d[n]); }
        float s = 0.0f;
        #pragma unroll
        for (int n = 0; n < 9; n++) { d[n] = __expf(d[n] - m); s += d[n]; }
        float inv = 1.0f / s;
        #pragma unroll
        for (int n = 0; n < 9; n++) d[n] *= inv;

        float4 o0 = make_float4(0.f, 0.f, 0.f, 0.f), o1 = o0;
        #pragma unroll
        for (int n = 0; n < 9; n++) {
            int dy = n / 3 - 1, dx = n - (n / 3) * 3 - 1;
            const float* vr = vbuf + base + (dy * HWD + dx) * APS;
            float4 v0 = *(const float4*)vr;
            float4 v1 = *(const float4*)(vr + 32);
            float a = d[n];
            o0.x += a * v0.x; o0.y += a * v0.y; o0.z += a * v0.z; o0.w += a * v0.w;
            o1.x += a * v1.x; o1.y += a * v1.y; o1.z += a * v1.z; o1.w += a * v1.w;
        }

        uint32_t h0a = xh32[hp * XSTR + cl * 2],      l0a = xl32[hp * XSTR + cl * 2];
        uint32_t h0b = xh32[hp * XSTR + cl * 2 + 1],  l0b = xl32[hp * XSTR + cl * 2 + 1];
        uint32_t h1a = xh32[hp * XSTR + 16 + cl * 2], l1a = xl32[hp * XSTR + 16 + cl * 2];
        uint32_t h1b = xh32[hp * XSTR + 17 + cl * 2], l1b = xl32[hp * XSTR + 17 + cl * 2];

        float t0 = o0.x + BFLO(h0a) + BFLO(l0a);
        float t1 = o0.y + BFHI(h0a) + BFHI(l0a);
        float t2 = o0.z + BFLO(h0b) + BFLO(l0b);
        float t3 = o0.w + BFHI(h0b) + BFHI(l0b);
        float t4 = o1.x + BFLO(h1a) + BFLO(l1a);
        float t5 = o1.y + BFHI(h1a) + BFHI(l1a);
        float t6 = o1.z + BFLO(h1b) + BFLO(l1b);
        float t7 = o1.w + BFHI(h1b) + BFHI(l1b);

        uint2 oh0, ol0, oh1, ol1;
        bfpair(t0, t1, oh0.x, ol0.x);
        bfpair(t2, t3, oh0.y, ol0.y);
        bfpair(t4, t5, oh1.x, ol1.x);
        bfpair(t6, t7, oh1.y, ol1.y);

        __nv_bfloat16* th = g_th + ((size_t)b * HWP + p) * 64;
        __nv_bfloat16* tl = g_tl + ((size_t)b * HWP + p) * 64;
        *(uint2*)(th + cl * 4)      = oh0;
        *(uint2*)(th + 32 + cl * 4) = oh1;
        *(uint2*)(tl + cl * 4)      = ol0;
        *(uint2*)(tl + 32 + cl * 4) = ol1;
    }
}

// ---------------------------------------------------------------------------
// Kernel 3: 3x3 conv + ReLU (R14 version, unchanged).
// ---------------------------------------------------------------------------
#define HSTR 72
#define HPX  130
#define OFF_AH 0
#define OFF_AL (3 * HPX * HSTR)
#define SMEM3_UNITS (2 * OFF_AL)

__global__ __launch_bounds__(256, 2) void conv_kernel(float* __restrict__ out) {
    extern __shared__ __nv_bfloat16 sm[];
    const int tid = threadIdx.x;
    const int wid = tid >> 5, lane = tid & 31;
    const int x0 = blockIdx.x * 128, y0 = blockIdx.y, b = blockIdx.z;

    {
        const __nv_bfloat16* srcs[2] = { g_th + (size_t)b * HWP * 64,
                                         g_tl + (size_t)b * HWP * 64 };
        #pragma unroll
        for (int hb = 0; hb < 2; hb++) {
            uint4* dst = (uint4*)(sm + (hb ? OFF_AL : OFF_AH));
            const __nv_bfloat16* s = srcs[hb];
            for (int u = tid; u < 3120; u += 256) {
                int r = u / 1040, rem = u - r * 1040;
                int px = rem >> 3, ch = rem & 7;
                int gy = y0 - 1 + r, gx = x0 - 1 + px;
                uint4 v = make_uint4(0u, 0u, 0u, 0u);
                if (gy >= 0 && gy < HH && gx >= 0 && gx < WW)
                    v = *(const uint4*)(s + ((size_t)(gy * WW + gx)) * 64 + ch * 8);
                dst[(r * HPX + px) * 9 + ch] = v;
            }
        }
    }
    __syncthreads();

    const int qt = lane >> 2, rt = lane & 3;
    const int ocg = wid & 1;
    const int pxg = wid >> 1;

    const int lm_m = lane >> 3, lm_r = lane & 7;
    const uint32_t sbase = (uint32_t)__cvta_generic_to_shared(sm);
    const uint32_t lane_off =
        ((uint32_t)((pxg * 32 + (lm_m >> 1) * 8 + lm_r) * HSTR + (lm_m & 1) * 8)) * 2;

    float acc[2][4][4];
    #pragma unroll
    for (int mt = 0; mt < 2; mt++)
        #pragma unroll
        for (int nt = 0; nt < 4; nt++)
            #pragma unroll
            for (int i = 0; i < 4; i++) acc[mt][nt][i] = 0.0f;

    #pragma unroll
    for (int tap = 0; tap < 9; tap++) {
        const int ky = tap / 3, kx = tap - ky * 3;
        const uint32_t ahi = sbase + lane_off + (uint32_t)((ky * HPX + kx) * HSTR) * 2;
        const uint32_t alo = ahi + (uint32_t)OFF_AL * 2;
        const uint4* wfh0 = g_wfh + (tap * 4 + 2 * ocg) * 128 + lane;
        const uint4* wfl0 = g_wfl + (tap * 4 + 2 * ocg) * 128 + lane;

        #pragma unroll
        for (int ks = 0; ks < 4; ks++) {
            uint4 Wh0 = __ldg(wfh0 + ks * 32);
            uint4 Wh1 = __ldg(wfh0 + 128 + ks * 32);
            uint4 Wl0 = __ldg(wfl0 + ks * 32);
            uint4 Wl1 = __ldg(wfl0 + 128 + ks * 32);
            const uint32_t ko = (uint32_t)(ks * 16) * 2;

            #pragma unroll
            for (int P = 0; P < 2; P++) {
                const uint32_t po = (uint32_t)(P * 16 * HSTR) * 2;
                uint32_t bh0, bh1, bh2, bh3, bl0, bl1, bl2, bl3;
                ldmx4(bh0, bh1, bh2, bh3, ahi + po + ko);
                ldmx4(bl0, bl1, bl2, bl3, alo + po + ko);
                mma16816(acc[0][2*P][0], acc[0][2*P][1], acc[0][2*P][2], acc[0][2*P][3],
                         Wh0.x, Wh0.y, Wh0.z, Wh0.w, bh0, bh1);
                mma16816(acc[0][2*P][0], acc[0][2*P][1], acc[0][2*P][2], acc[0][2*P][3],
                         Wl0.x, Wl0.y, Wl0.z, Wl0.w, bh0, bh1);
                mma16816(acc[0][2*P][0], acc[0][2*P][1], acc[0][2*P][2], acc[0][2*P][3],
                         Wh0.x, Wh0.y, Wh0.z, Wh0.w, bl0, bl1);
                mma16816(acc[0][2*P+1][0], acc[0][2*P+1][1], acc[0][2*P+1][2], acc[0][2*P+1][3],
                         Wh0.x, Wh0.y, Wh0.z, Wh0.w, bh2, bh3);
                mma16816(acc[0][2*P+1][0], acc[0][2*P+1][1], acc[0][2*P+1][2], acc[0][2*P+1][3],
                         Wl0.x, Wl0.y, Wl0.z, Wl0.w, bh2, bh3);
                mma16816(acc[0][2*P+1][0], acc[0][2*P+1][1], acc[0][2*P+1][2], acc[0][2*P+1][3],
                         Wh0.x, Wh0.y, Wh0.z, Wh0.w, bl2, bl3);
                mma16816(acc[1][2*P][0], acc[1][2*P][1], acc[1][2*P][2], acc[1][2*P][3],
                         Wh1.x, Wh1.y, Wh1.z, Wh1.w, bh0, bh1);
                mma16816(acc[1][2*P][0], acc[1][2*P][1], acc[1][2*P][2], acc[1][2*P][3],
                         Wl1.x, Wl1.y, Wl1.z, Wl1.w, bh0, bh1);
                mma16816(acc[1][2*P][0], acc[1][2*P][1], acc[1][2*P][2], acc[1][2*P][3],
                         Wh1.x, Wh1.y, Wh1.z, Wh1.w, bl0, bl1);
                mma16816(acc[1][2*P+1][0], acc[1][2*P+1][1], acc[1][2*P+1][2], acc[1][2*P+1][3],
                         Wh1.x, Wh1.y, Wh1.z, Wh1.w, bh2, bh3);
                mma16816(acc[1][2*P+1][0], acc[1][2*P+1][1], acc[1][2*P+1][2], acc[1][2*P+1][3],
                         Wl1.x, Wl1.y, Wl1.z, Wl1.w, bh2, bh3);
                mma16816(acc[1][2*P+1][0], acc[1][2*P+1][1], acc[1][2*P+1][2], acc[1][2*P+1][3],
                         Wh1.x, Wh1.y, Wh1.z, Wh1.w, bl2, bl3);
            }
        }
    }

    float* ob = out + (size_t)b * CC * HWP + (size_t)y0 * WW + x0;
    #pragma unroll
    for (int mt = 0; mt < 2; mt++) {
        const int oc = ocg * 32 + mt * 16 + qt;
        #pragma unroll
        for (int nt = 0; nt < 4; nt++) {
            const int px = pxg * 32 + nt * 8 + 2 * rt;
            float2 v0 = make_float2(fmaxf(acc[mt][nt][0], 0.f), fmaxf(acc[mt][nt][1], 0.f));
            float2 v1 = make_float2(fmaxf(acc[mt][nt][2], 0.f), fmaxf(acc[mt][nt][3], 0.f));
            *(float2*)(ob + (size_t)oc * HWP + px)       = v0;
            *(float2*)(ob + (size_t)(oc + 8) * HWP + px) = v1;
        }
    }
}

// ---------------------------------------------------------------------------
extern "C" void kernel_launch(void* const* d_in, const int* in_sizes, int n_in,
                              void* d_out, int out_size) {
    const float* x     = (const float*)d_in[0];
    const float* w_qkv = (const float*)d_in[1];
    const float* b_qkv = (const float*)d_in[2];
    const float* w_mlp = (const float*)d_in[3];
    float* out = (float*)d_out;

    const int SMEM3 = SMEM3_UNITS * 2;
    cudaFuncSetAttribute(fused_kernel, cudaFuncAttributeMaxDynamicSharedMemorySize, FUSED_SMEM);
    cudaFuncSetAttribute(conv_kernel,  cudaFuncAttributeMaxDynamicSharedMemorySize, SMEM3);

    prep_kernel<<<24, 256>>>(w_mlp, w_qkv);
    fused_kernel<<<dim3(WW / 16, HH / 4, BB), 384, FUSED_SMEM>>>(x, b_qkv);
    conv_kernel<<<dim3(WW / 128, HH, BB), 256, SMEM3>>>(out);
}

// round 17
// speedup vs baseline: 1.0703x; 1.0703x over previous
#include <cuda_runtime.h>
#include <cuda_bf16.h>
#include <cstdint>

#define HH 256
#define WW 256
#define HWP 65536
#define CC 64
#define BB 4

// ---------------------------------------------------------------- scratch
__device__ __align__(16) __nv_bfloat16 g_th[(size_t)BB * HWP * CC];  // [b][p][c] hi
__device__ __align__(16) __nv_bfloat16 g_tl[(size_t)BB * HWP * CC];  // [b][p][c] lo
__device__ uint4 g_wfh[9 * 4 * 4 * 32];    // conv weights frag-order hi
__device__ uint4 g_wfl[9 * 4 * 4 * 32];    // lo
__device__ uint4 g_wqh[12 * 4 * 32];       // qkv weights frag-order hi
__device__ uint4 g_wql[12 * 4 * 32];       // lo

#define BFLO(u) __uint_as_float((u) << 16)
#define BFHI(u) __uint_as_float((u) & 0xffff0000u)

// ---------------------------------------------------------------------------
__device__ __forceinline__ void mma16816(float& d0, float& d1, float& d2, float& d3,
                                         uint32_t a0, uint32_t a1, uint32_t a2, uint32_t a3,
                                         uint32_t b0, uint32_t b1) {
    asm volatile(
        "mma.sync.aligned.m16n8k16.row.col.f32.bf16.bf16.f32 "
        "{%0,%1,%2,%3}, {%4,%5,%6,%7}, {%8,%9}, {%0,%1,%2,%3};"
        : "+f"(d0), "+f"(d1), "+f"(d2), "+f"(d3)
        : "r"(a0), "r"(a1), "r"(a2), "r"(a3), "r"(b0), "r"(b1));
}

__device__ __forceinline__ void ldmx4(uint32_t& r0, uint32_t& r1, uint32_t& r2,
                                      uint32_t& r3, uint32_t saddr) {
    asm volatile("ldmatrix.sync.aligned.m8n8.x4.shared.b16 {%0,%1,%2,%3}, [%4];"
                 : "=r"(r0), "=r"(r1), "=r"(r2), "=r"(r3) : "r"(saddr));
}

__device__ __forceinline__ void ldmx2(uint32_t& r0, uint32_t& r1, uint32_t saddr) {
    asm volatile("ldmatrix.sync.aligned.m8n8.x2.shared.b16 {%0,%1}, [%2];"
                 : "=r"(r0), "=r"(r1) : "r"(saddr));
}

__device__ __forceinline__ void cpasync16(uint32_t dst, const void* src) {
    asm volatile("cp.async.cg.shared.global [%0], [%1], 16;"
                 :: "r"(dst), "l"(src) : "memory");
}

__device__ __forceinline__ void bfpair(float w0, float w1, uint32_t& h, uint32_t& l) {
    __nv_bfloat16 h0 = __float2bfloat16_rn(w0);
    __nv_bfloat16 h1 = __float2bfloat16_rn(w1);
    __nv_bfloat16 l0 = __float2bfloat16_rn(w0 - __bfloat162float(h0));
    __nv_bfloat16 l1 = __float2bfloat16_rn(w1 - __bfloat162float(h1));
    h = (uint32_t)__bfloat16_as_ushort(h0) | ((uint32_t)__bfloat16_as_ushort(h1) << 16);
    l = (uint32_t)__bfloat16_as_ushort(l0) | ((uint32_t)__bfloat16_as_ushort(l1) << 16);
}

// ---------------------------------------------------------------------------
// Kernel 0: merged weight prep (unchanged).
// ---------------------------------------------------------------------------
__global__ void prep_kernel(const float* __restrict__ wm,
                            const float* __restrict__ wq) {
    if (blockIdx.x < 18) {
        int e = blockIdx.x * 256 + threadIdx.x;
        if (e >= 4608) return;
        int tap = e / 512, rem = e & 511;
        int ocg = rem >> 7, rem2 = rem & 127;
        int ks = rem2 >> 5, lane = rem2 & 31;
        int qt = lane >> 2, rt = lane & 3;
        int oc = ocg * 16 + qt, c = ks * 16 + 2 * rt;
        uint4 hv, lv;
        bfpair(wm[oc * 576 + c * 9 + tap],       wm[oc * 576 + (c + 1) * 9 + tap],       hv.x, lv.x);
        bfpair(wm[(oc + 8) * 576 + c * 9 + tap], wm[(oc + 8) * 576 + (c + 1) * 9 + tap], hv.y, lv.y);
        bfpair(wm[oc * 576 + (c + 8) * 9 + tap], wm[oc * 576 + (c + 9) * 9 + tap],       hv.z, lv.z);
        bfpair(wm[(oc + 8) * 576 + (c + 8) * 9 + tap], wm[(oc + 8) * 576 + (c + 9) * 9 + tap], hv.w, lv.w);
        g_wfh[e] = hv;
        g_wfl[e] = lv;
    } else {
        int e = (blockIdx.x - 18) * 256 + threadIdx.x;
        if (e >= 1536) return;
        int lane = e & 31, ks = (e >> 5) & 3, ocg = e >> 7;
        int qt = lane >> 2, rt = lane & 3;
        int oc = ocg * 16 + qt, c = ks * 16 + 2 * rt;
        uint4 hv, lv;
        bfpair(wq[oc * 64 + c],           wq[oc * 64 + c + 1],           hv.x, lv.x);
        bfpair(wq[(oc + 8) * 64 + c],     wq[(oc + 8) * 64 + c + 1],     hv.y, lv.y);
        bfpair(wq[oc * 64 + c + 8],       wq[oc * 64 + c + 9],           hv.z, lv.z);
        bfpair(wq[(oc + 8) * 64 + c + 8], wq[(oc + 8) * 64 + c + 9],     hv.w, lv.w);
        g_wqh[e] = hv;
        g_wql[e] = lv;
    }
}

// ---------------------------------------------------------------------------
// Kernel 1: FUSED qkv (HMMA) + window attention + residual (R15 version).
// ---------------------------------------------------------------------------
#define HWD 18
#define HPXN 108
#define HPAD 112
#define XSTR 36
#define APS 68
#define OFF_XL (HPAD * XSTR)                 // 4032  u32
#define OFF_QB (2 * HPAD * XSTR)             // 8064
#define OFF_KB (OFF_QB + 64 * APS)           // 12416
#define OFF_VB (OFF_KB + HPAD * APS)         // 20032
#define FUSED_SMEM ((OFF_VB + HPAD * APS) * 4)   // 110592 B

__global__ __launch_bounds__(384, 2) void fused_kernel(const float* __restrict__ x,
                                                       const float* __restrict__ bq) {
    extern __shared__ uint32_t fs[];
    uint32_t* xh32 = fs;
    uint32_t* xl32 = fs + OFF_XL;
    float* qbuf = (float*)(fs + OFF_QB);
    float* kbuf = (float*)(fs + OFF_KB);
    float* vbuf = (float*)(fs + OFF_VB);

    const int tid = threadIdx.x;
    const int wid = tid >> 5, lane = tid & 31;
    const int qt = lane >> 2, rt = lane & 3;
    const int x0 = blockIdx.x * 16, y0 = blockIdx.y * 4;
    const int b = blockIdx.z;

    // ---- Phase 1: stage x halo as bf16 hi/lo pairs ----
    for (int e = tid; e < 512; e += 384) {     // 4 c-groups x 128 hp slots
        int hp = e & 127;
        int g4 = e >> 7;
        if (hp >= HPAD) continue;
        int hy = hp / HWD, hx = hp - hy * HWD;
        int gy = y0 - 1 + hy, gx = x0 - 1 + hx;
        bool ok = (hp < HPXN) && gy >= 0 && gy < HH && gx >= 0 && gx < WW;
        const float* xp = x + (size_t)b * CC * HWP + gy * WW + gx;
        #pragma unroll
        for (int j = 0; j < 8; j++) {
            int c = g4 * 16 + 2 * j;
            float v0 = 0.f, v1 = 0.f;
            if (ok) { v0 = xp[(size_t)c * HWP]; v1 = xp[(size_t)(c + 1) * HWP]; }
            uint32_t h, l;
            bfpair(v0, v1, h, l);
            xh32[hp * XSTR + (c >> 1)] = h;
            xl32[hp * XSTR + (c >> 1)] = l;
        }
    }
    __syncthreads();

    // ---- Phase 2: qkv MMA over halo columns (ldmatrix B-frags) ----
    {
        const uint4* wqh = g_wqh + wid * 128 + lane;
        const uint4* wql = g_wql + wid * 128 + lane;
        const int chunk = wid >> 2;              // 0=q 1=k 2=v
        const int ocl = (wid & 3) * 16 + qt;
        const float b0v = __ldg(bq + wid * 16 + qt);
        const float b1v = __ldg(bq + wid * 16 + qt + 8);
        float* dst = (chunk == 1) ? kbuf : vbuf;
        const bool isq = (chunk == 0);

        const int lm_m = lane >> 3, lm_r = lane & 7;
        const uint32_t sbx = (uint32_t)__cvta_generic_to_shared(xh32);
        const uint32_t lo4 = (uint32_t)(((lm_m >> 1) * 8 + lm_r) * XSTR + (lm_m & 1) * 4) * 4u;
        const uint32_t lo2 = (uint32_t)((lane & 7) * XSTR + ((lane >> 3) & 1) * 4) * 4u;
        const uint32_t XLB = (uint32_t)OFF_XL * 4u;

        #pragma unroll
        for (int half = 0; half < 2; half++) {
            const int ntb = half * 7;
            float acc[7][4];
            #pragma unroll
            for (int nt = 0; nt < 7; nt++)
                #pragma unroll
                for (int i = 0; i < 4; i++) acc[nt][i] = 0.0f;

            #pragma unroll
            for (int ks = 0; ks < 4; ks++) {
                uint4 Wh = __ldg(wqh + ks * 32);
                uint4 Wl = __ldg(wql + ks * 32);
                const uint32_t kob = (uint32_t)(ks * 8) * 4u;

                #pragma unroll
                for (int p = 0; p < 3; p++) {
                    if (isq && half == 0 && p == 0) continue;
                    const uint32_t ra = sbx + lo4 + (uint32_t)((ntb + 2 * p) * 8 * XSTR) * 4u + kob;
                    uint32_t bh0, bh1, bh2, bh3, bl0, bl1, bl2, bl3;
                    ldmx4(bh0, bh1, bh2, bh3, ra);
                    ldmx4(bl0, bl1, bl2, bl3, ra + XLB);
                    mma16816(acc[2*p][0], acc[2*p][1], acc[2*p][2], acc[2*p][3],
                             Wh.x, Wh.y, Wh.z, Wh.w, bh0, bh1);
                    mma16816(acc[2*p][0], acc[2*p][1], acc[2*p][2], acc[2*p][3],
                             Wl.x, Wl.y, Wl.z, Wl.w, bh0, bh1);
                    mma16816(acc[2*p][0], acc[2*p][1], acc[2*p][2], acc[2*p][3],
                             Wh.x, Wh.y, Wh.z, Wh.w, bl0, bl1);
                    mma16816(acc[2*p+1][0], acc[2*p+1][1], acc[2*p+1][2], acc[2*p+1][3],
                             Wh.x, Wh.y, Wh.z, Wh.w, bh2, bh3);
                    mma16816(acc[2*p+1][0], acc[2*p+1][1], acc[2*p+1][2], acc[2*p+1][3],
                             Wl.x, Wl.y, Wl.z, Wl.w, bh2, bh3);
                    mma16816(acc[2*p+1][0], acc[2*p+1][1], acc[2*p+1][2], acc[2*p+1][3],
                             Wh.x, Wh.y, Wh.z, Wh.w, bl2, bl3);
                }
                if (!(isq && half == 1)) {
                    const uint32_t ra = sbx + lo2 + (uint32_t)((ntb + 6) * 8 * XSTR) * 4u + kob;
                    uint32_t bh0, bh1, bl0, bl1;
                    ldmx2(bh0, bh1, ra);
                    ldmx2(bl0, bl1, ra + XLB);
                    mma16816(acc[6][0], acc[6][1], acc[6][2], acc[6][3],
                             Wh.x, Wh.y, Wh.z, Wh.w, bh0, bh1);
                    mma16816(acc[6][0], acc[6][1], acc[6][2], acc[6][3],
                             Wl.x, Wl.y, Wl.z, Wl.w, bh0, bh1);
                    mma16816(acc[6][0], acc[6][1], acc[6][2], acc[6][3],
                             Wh.x, Wh.y, Wh.z, Wh.w, bl0, bl1);
                }
            }

            #pragma unroll
            for (int nt = 0; nt < 7; nt++) {
                #pragma unroll
                for (int j = 0; j < 2; j++) {
                    int hpj = (ntb + nt) * 8 + 2 * rt + j;
                    int hy = hpj / HWD, hx = hpj - hy * HWD;
                    if (chunk == 0) {
                        if (hy >= 1 && hy <= 4 && hx >= 1 && hx <= 16) {
                            int ci = (hy - 1) * 16 + (hx - 1);
                            qbuf[ci * APS + ocl]     = acc[nt][j]     + b0v;
                            qbuf[ci * APS + ocl + 8] = acc[nt][2 + j] + b1v;
                        }
                    } else {
                        int gy = y0 - 1 + hy, gx = x0 - 1 + hx;
                        bool ok = (hpj < HPXN) && gy >= 0 && gy < HH && gx >= 0 && gx < WW;
                        dst[hpj * APS + ocl]     = ok ? acc[nt][j]     + b0v : 0.0f;
                        dst[hpj * APS + ocl + 8] = ok ? acc[nt][2 + j] + b1v : 0.0f;
                    }
                }
            }
        }
    }
    __syncthreads();

    // ---- Phase 3: attention from smem ----
    const int g = lane >> 3, cl = lane & 7;
    #pragma unroll
    for (int iter = 0; iter < 2; iter++) {
        const int pxi = iter * 48 + wid * 4 + g;   // 0..95
        if (pxi >= 64) break;
        const int tx = pxi & 15, ty = pxi >> 4;
        const int hp = (ty + 1) * HWD + (tx + 1);
        const int p = (y0 + ty) * WW + x0 + tx;

        float4 q0 = *(const float4*)(qbuf + pxi * APS + cl * 4);
        float4 q1 = *(const float4*)(qbuf + pxi * APS + cl * 4 + 32);
        const int base = hp * APS + cl * 4;

        float d[9];
        #pragma unroll
        for (int n = 0; n < 9; n++) {
            int dy = n / 3 - 1, dx = n - (n / 3) * 3 - 1;
            const float* kr = kbuf + base + (dy * HWD + dx) * APS;
            float4 k0 = *(const float4*)kr;
            float4 k1 = *(const float4*)(kr + 32);
            d[n] = q0.x * k0.x + q0.y * k0.y + q0.z * k0.z + q0.w * k0.w
                 + q1.x * k1.x + q1.y * k1.y + q1.z * k1.z + q1.w * k1.w;
        }
        #pragma unroll
        for (int ofs = 4; ofs > 0; ofs >>= 1)
            #pragma unroll
            for (int n = 0; n < 9; n++)
                d[n] += __shfl_xor_sync(0xffffffffu, d[n], ofs);

        float m = -1e30f;
        #pragma unroll
        for (int n = 0; n < 9; n++) { d[n] *= 0.125f; m = fmaxf(m, d[n]); }
        float s = 0.0f;
        #pragma unroll
        for (int n = 0; n < 9; n++) { d[n] = __expf(d[n] - m); s += d[n]; }
        float inv = 1.0f / s;
        #pragma unroll
        for (int n = 0; n < 9; n++) d[n] *= inv;

        float4 o0 = make_float4(0.f, 0.f, 0.f, 0.f), o1 = o0;
        #pragma unroll
        for (int n = 0; n < 9; n++) {
            int dy = n / 3 - 1, dx = n - (n / 3) * 3 - 1;
            const float* vr = vbuf + base + (dy * HWD + dx) * APS;
            float4 v0 = *(const float4*)vr;
            float4 v1 = *(const float4*)(vr + 32);
            float a = d[n];
            o0.x += a * v0.x; o0.y += a * v0.y; o0.z += a * v0.z; o0.w += a * v0.w;
            o1.x += a * v1.x; o1.y += a * v1.y; o1.z += a * v1.z; o1.w += a * v1.w;
        }

        uint32_t h0a = xh32[hp * XSTR + cl * 2],      l0a = xl32[hp * XSTR + cl * 2];
        uint32_t h0b = xh32[hp * XSTR + cl * 2 + 1],  l0b = xl32[hp * XSTR + cl * 2 + 1];
        uint32_t h1a = xh32[hp * XSTR + 16 + cl * 2], l1a = xl32[hp * XSTR + 16 + cl * 2];
        uint32_t h1b = xh32[hp * XSTR + 17 + cl * 2], l1b = xl32[hp * XSTR + 17 + cl * 2];

        float t0 = o0.x + BFLO(h0a) + BFLO(l0a);
        float t1 = o0.y + BFHI(h0a) + BFHI(l0a);
        float t2 = o0.z + BFLO(h0b) + BFLO(l0b);
        float t3 = o0.w + BFHI(h0b) + BFHI(l0b);
        float t4 = o1.x + BFLO(h1a) + BFLO(l1a);
        float t5 = o1.y + BFHI(h1a) + BFHI(l1a);
        float t6 = o1.z + BFLO(h1b) + BFLO(l1b);
        float t7 = o1.w + BFHI(h1b) + BFHI(l1b);

        uint2 oh0, ol0, oh1, ol1;
        bfpair(t0, t1, oh0.x, ol0.x);
        bfpair(t2, t3, oh0.y, ol0.y);
        bfpair(t4, t5, oh1.x, ol1.x);
        bfpair(t6, t7, oh1.y, ol1.y);

        __nv_bfloat16* th = g_th + ((size_t)b * HWP + p) * 64;
        __nv_bfloat16* tl = g_tl + ((size_t)b * HWP + p) * 64;
        *(uint2*)(th + cl * 4)      = oh0;
        *(uint2*)(th + 32 + cl * 4) = oh1;
        *(uint2*)(tl + cl * 4)      = ol0;
        *(uint2*)(tl + 32 + cl * 4) = ol1;
    }
}

// ---------------------------------------------------------------------------
// Kernel 3: 3x3 conv + ReLU (R14 tiling; staging now via cp.async.cg).
// ---------------------------------------------------------------------------
#define HSTR 72
#define HPX  130
#define OFF_AH 0
#define OFF_AL (3 * HPX * HSTR)
#define SMEM3_UNITS (2 * OFF_AL)

__global__ __launch_bounds__(256, 2) void conv_kernel(float* __restrict__ out) {
    extern __shared__ __nv_bfloat16 sm[];
    const int tid = threadIdx.x;
    const int wid = tid >> 5, lane = tid & 31;
    const int x0 = blockIdx.x * 128, y0 = blockIdx.y, b = blockIdx.z;

    // ---- stage halo hi/lo via cp.async (16B chunks); OOB -> zero STS ----
    {
        const uint32_t sb0 = (uint32_t)__cvta_generic_to_shared(sm);
        const __nv_bfloat16* srcs[2] = { g_th + (size_t)b * HWP * 64,
                                         g_tl + (size_t)b * HWP * 64 };
        #pragma unroll
        for (int hb = 0; hb < 2; hb++) {
            const uint32_t dbase = sb0 + (uint32_t)((hb ? OFF_AL : OFF_AH)) * 2;
            const __nv_bfloat16* s = srcs[hb];
            for (int u = tid; u < 3120; u += 256) {
                int r = u / 1040, rem = u - r * 1040;
                int px = rem >> 3, ch = rem & 7;
                int gy = y0 - 1 + r, gx = x0 - 1 + px;
                uint32_t dst = dbase + (uint32_t)(((r * HPX + px) * 9 + ch) * 16);
                if (gy >= 0 && gy < HH && gx >= 0 && gx < WW) {
                    cpasync16(dst, s + ((size_t)(gy * WW + gx)) * 64 + ch * 8);
                } else {
                    *(uint4*)(sm + (hb ? OFF_AL : OFF_AH) + (size_t)((r * HPX + px) * 9 + ch) * 8)
                        = make_uint4(0u, 0u, 0u, 0u);
                }
            }
        }
        asm volatile("cp.async.commit_group;" ::: "memory");
        asm volatile("cp.async.wait_group 0;" ::: "memory");
    }
    __syncthreads();

    const int qt = lane >> 2, rt = lane & 3;
    const int ocg = wid & 1;
    const int pxg = wid >> 1;

    const int lm_m = lane >> 3, lm_r = lane & 7;
    const uint32_t sbase = (uint32_t)__cvta_generic_to_shared(sm);
    const uint32_t lane_off =
        ((uint32_t)((pxg * 32 + (lm_m >> 1) * 8 + lm_r) * HSTR + (lm_m & 1) * 8)) * 2;

    float acc[2][4][4];
    #pragma unroll
    for (int mt = 0; mt < 2; mt++)
        #pragma unroll
        for (int nt = 0; nt < 4; nt++)
            #pragma unroll
            for (int i = 0; i < 4; i++) acc[mt][nt][i] = 0.0f;

    #pragma unroll
    for (int tap = 0; tap < 9; tap++) {
        const int ky = tap / 3, kx = tap - ky * 3;
        const uint32_t ahi = sbase + lane_off + (uint32_t)((ky * HPX + kx) * HSTR) * 2;
        const uint32_t alo = ahi + (uint32_t)OFF_AL * 2;
        const uint4* wfh0 = g_wfh + (tap * 4 + 2 * ocg) * 128 + lane;
        const uint4* wfl0 = g_wfl + (tap * 4 + 2 * ocg) * 128 + lane;

        #pragma unroll
        for (int ks = 0; ks < 4; ks++) {
            uint4 Wh0 = __ldg(wfh0 + ks * 32);
            uint4 Wh1 = __ldg(wfh0 + 128 + ks * 32);
            uint4 Wl0 = __ldg(wfl0 + ks * 32);
            uint4 Wl1 = __ldg(wfl0 + 128 + ks * 32);
            const uint32_t ko = (uint32_t)(ks * 16) * 2;

            #pragma unroll
            for (int P = 0; P < 2; P++) {
                const uint32_t po = (uint32_t)(P * 16 * HSTR) * 2;
                uint32_t bh0, bh1, bh2, bh3, bl0, bl1, bl2, bl3;
                ldmx4(bh0, bh1, bh2, bh3, ahi + po + ko);
                ldmx4(bl0, bl1, bl2, bl3, alo + po + ko);
                mma16816(acc[0][2*P][0], acc[0][2*P][1], acc[0][2*P][2], acc[0][2*P][3],
                         Wh0.x, Wh0.y, Wh0.z, Wh0.w, bh0, bh1);
                mma16816(acc[0][2*P][0], acc[0][2*P][1], acc[0][2*P][2], acc[0][2*P][3],
                         Wl0.x, Wl0.y, Wl0.z, Wl0.w, bh0, bh1);
                mma16816(acc[0][2*P][0], acc[0][2*P][1], acc[0][2*P][2], acc[0][2*P][3],
                         Wh0.x, Wh0.y, Wh0.z, Wh0.w, bl0, bl1);
                mma16816(acc[0][2*P+1][0], acc[0][2*P+1][1], acc[0][2*P+1][2], acc[0][2*P+1][3],
                         Wh0.x, Wh0.y, Wh0.z, Wh0.w, bh2, bh3);
                mma16816(acc[0][2*P+1][0], acc[0][2*P+1][1], acc[0][2*P+1][2], acc[0][2*P+1][3],
                         Wl0.x, Wl0.y, Wl0.z, Wl0.w, bh2, bh3);
                mma16816(acc[0][2*P+1][0], acc[0][2*P+1][1], acc[0][2*P+1][2], acc[0][2*P+1][3],
                         Wh0.x, Wh0.y, Wh0.z, Wh0.w, bl2, bl3);
                mma16816(acc[1][2*P][0], acc[1][2*P][1], acc[1][2*P][2], acc[1][2*P][3],
                         Wh1.x, Wh1.y, Wh1.z, Wh1.w, bh0, bh1);
                mma16816(acc[1][2*P][0], acc[1][2*P][1], acc[1][2*P][2], acc[1][2*P][3],
                         Wl1.x, Wl1.y, Wl1.z, Wl1.w, bh0, bh1);
                mma16816(acc[1][2*P][0], acc[1][2*P][1], acc[1][2*P][2], acc[1][2*P][3],
                         Wh1.x, Wh1.y, Wh1.z, Wh1.w, bl0, bl1);
                mma16816(acc[1][2*P+1][0], acc[1][2*P+1][1], acc[1][2*P+1][2], acc[1][2*P+1][3],
                         Wh1.x, Wh1.y, Wh1.z, Wh1.w, bh2, bh3);
                mma16816(acc[1][2*P+1][0], acc[1][2*P+1][1], acc[1][2*P+1][2], acc[1][2*P+1][3],
                         Wl1.x, Wl1.y, Wl1.z, Wl1.w, bh2, bh3);
                mma16816(acc[1][2*P+1][0], acc[1][2*P+1][1], acc[1][2*P+1][2], acc[1][2*P+1][3],
                         Wh1.x, Wh1.y, Wh1.z, Wh1.w, bl2, bl3);
            }
        }
    }

    float* ob = out + (size_t)b * CC * HWP + (size_t)y0 * WW + x0;
    #pragma unroll
    for (int mt = 0; mt < 2; mt++) {
        const int oc = ocg * 32 + mt * 16 + qt;
        #pragma unroll
        for (int nt = 0; nt < 4; nt++) {
            const int px = pxg * 32 + nt * 8 + 2 * rt;
            float2 v0 = make_float2(fmaxf(acc[mt][nt][0], 0.f), fmaxf(acc[mt][nt][1], 0.f));
            float2 v1 = make_float2(fmaxf(acc[mt][nt][2], 0.f), fmaxf(acc[mt][nt][3], 0.f));
            *(float2*)(ob + (size_t)oc * HWP + px)       = v0;
            *(float2*)(ob + (size_t)(oc + 8) * HWP + px) = v1;
        }
    }
}

// ---------------------------------------------------------------------------
extern "C" void kernel_launch(void* const* d_in, const int* in_sizes, int n_in,
                              void* d_out, int out_size) {
    const float* x     = (const float*)d_in[0];
    const float* w_qkv = (const float*)d_in[1];
    const float* b_qkv = (const float*)d_in[2];
    const float* w_mlp = (const float*)d_in[3];
    float* out = (float*)d_out;

    const int SMEM3 = SMEM3_UNITS * 2;
    cudaFuncSetAttribute(fused_kernel, cudaFuncAttributeMaxDynamicSharedMemorySize, FUSED_SMEM);
    cudaFuncSetAttribute(conv_kernel,  cudaFuncAttributeMaxDynamicSharedMemorySize, SMEM3);

    prep_kernel<<<24, 256>>>(w_mlp, w_qkv);
    fused_kernel<<<dim3(WW / 16, HH / 4, BB), 384, FUSED_SMEM>>>(x, b_qkv);
    conv_kernel<<<dim3(WW / 128, HH, BB), 256, SMEM3>>>(out);
}